// round 5
// baseline (speedup 1.0000x reference)
#include <cuda_runtime.h>

// VanillaSSM via exact diagonal recurrence (== reference FFT conv):
//   u[d,n](l) = A_bar[d,n]*u(l-1) + x[b,l,d]
//   y[b,l,d]  = sum_n (C*B_bar)[d,n]*u[d,n](l) + D[d]*x[b,l,d]
// A = -exp(log_A); A_bar = exp(DT*A); B_bar = (A_bar-1)/A * B_param.
//
// Warp-autonomous: each warp owns 4 d-streams for one b. Lane owns 8 states
// (4 packed f32x2 regs); 8 lanes per d. Per 32-step round: x tile prefetched
// a round ahead (LDG never on critical path), staged in warp-private
// double-buffered smem (syncwarp only, no block barriers). Outputs reduced
// across the 8 group lanes with a shuffle butterfly batched over 16 steps,
// then moved to store layout with one shuffle transpose; skip connection
// fused at the store using the kept prefetch registers.

namespace {

constexpr int BATCH   = 8;
constexpr int L       = 2048;
constexpr int D_MODEL = 1024;
constexpr int NSTATE  = 64;
constexpr float DT    = 0.1f;

constexpr int T       = 32;        // timesteps per round
constexpr int NROUNDS = L / T;     // 64
constexpr int THREADS = 64;        // 2 warps/block; 8 d per block
constexpr int XSTR    = 40;        // per-group row stride (floats): 8j+i bank-bijective

__device__ __forceinline__ unsigned long long pack2(float lo, float hi) {
    unsigned long long r;
    asm("mov.b64 %0, {%1, %2};" : "=l"(r) : "f"(lo), "f"(hi));
    return r;
}
__device__ __forceinline__ void unpack2(unsigned long long v, float& lo, float& hi) {
    asm("mov.b64 {%0, %1}, %2;" : "=f"(lo), "=f"(hi) : "l"(v));
}
__device__ __forceinline__ unsigned long long mul2(unsigned long long a, unsigned long long b) {
    unsigned long long r;
    asm("mul.rn.f32x2 %0, %1, %2;" : "=l"(r) : "l"(a), "l"(b));
    return r;
}
__device__ __forceinline__ unsigned long long fma2(unsigned long long a, unsigned long long b,
                                                   unsigned long long c) {
    unsigned long long r;
    asm("fma.rn.f32x2 %0, %1, %2, %3;" : "=l"(r) : "l"(a), "l"(b), "l"(c));
    return r;
}

__global__ __launch_bounds__(THREADS)
void ssm_scan_kernel(const float* __restrict__ x,
                     const float* __restrict__ log_A,
                     const float* __restrict__ Bp,
                     const float* __restrict__ Cp,
                     const float* __restrict__ Dp,
                     float* __restrict__ y)
{
    __shared__ float xs[2][2][4 * XSTR];   // [warp][buf][group*XSTR + t]

    const int b    = blockIdx.y;
    const int tid  = threadIdx.x;
    const int w    = tid >> 5;
    const int lane = tid & 31;
    const int g    = lane >> 3;            // d-group within warp (0..3)
    const int gl   = lane & 7;             // lane within group
    const int d0w  = blockIdx.x * 8 + w * 4;
    const int d    = d0w + g;

    // ---- coefficients: lane owns states n = gl*4+j paired with n+32 ----
    unsigned long long a01[4], k01[4];
    {
        const int cb = d * NSTATE + gl * 4;
        const float4 laL = *(const float4*)&log_A[cb];
        const float4 laH = *(const float4*)&log_A[cb + 32];
        const float4 bL  = *(const float4*)&Bp[cb];
        const float4 bH  = *(const float4*)&Bp[cb + 32];
        const float4 cL  = *(const float4*)&Cp[cb];
        const float4 cH  = *(const float4*)&Cp[cb + 32];
        const float* laLp = &laL.x; const float* laHp = &laH.x;
        const float* bLp  = &bL.x;  const float* bHp  = &bH.x;
        const float* cLp  = &cL.x;  const float* cHp  = &cH.x;
#pragma unroll
        for (int j = 0; j < 4; ++j) {
            const float AL = -expf(laLp[j]);
            const float AH = -expf(laHp[j]);
            const float aL = expf(DT * AL);
            const float aH = expf(DT * AH);
            const float kL = (aL - 1.0f) / AL * bLp[j] * cLp[j];
            const float kH = (aH - 1.0f) / AH * bHp[j] * cHp[j];
            a01[j] = pack2(aL, aH);
            k01[j] = pack2(kL, kH);
        }
    }

    // staging role: lane = si*4 + sj  ->  (l = l0 + si + 8k, d = d0w + sj)
    const int si = lane >> 2;
    const int sj = lane & 3;
    const float Dd = Dp[d0w + sj];
    const float* xg = x + (long)b * L * D_MODEL + d0w + sj;
    float*       yg = y + (long)b * L * D_MODEL + d0w + sj;

    // prefetch tile 0
    float xpre[4], xcur[4];
#pragma unroll
    for (int k = 0; k < 4; ++k)
        xpre[k] = xg[(si + 8 * k) * D_MODEL];

    unsigned long long u0 = 0ull, u1 = 0ull, u2 = 0ull, u3 = 0ull;

    for (int r = 0; r < NROUNDS; ++r) {
        const int l0 = r * T;
        float* xb = xs[w][r & 1];

        // stage tile r (conflict-free: addr mod 32 = 8*sj + si, bijective)
#pragma unroll
        for (int k = 0; k < 4; ++k) {
            xcur[k] = xpre[k];
            xb[sj * XSTR + si + 8 * k] = xpre[k];
        }
        __syncwarp();

        // prefetch tile r+1 (overlaps with the 32-step compute below)
        if (r + 1 < NROUNDS) {
#pragma unroll
            for (int k = 0; k < 4; ++k)
                xpre[k] = xg[(l0 + T + si + 8 * k) * D_MODEL];
        }

        float y_out[4];
#pragma unroll
        for (int tb = 0; tb < T; tb += 16) {
            float v[16];
#pragma unroll
            for (int q = 0; q < 16; q += 4) {
                const float4 xq = *(const float4*)&xb[g * XSTR + tb + q];
                const float* xe = &xq.x;
#pragma unroll
                for (int i2 = 0; i2 < 4; ++i2) {
                    const unsigned long long xx = pack2(xe[i2], xe[i2]);
                    u0 = fma2(a01[0], u0, xx);
                    u1 = fma2(a01[1], u1, xx);
                    u2 = fma2(a01[2], u2, xx);
                    u3 = fma2(a01[3], u3, xx);
                    unsigned long long acc = mul2(k01[0], u0);
                    acc = fma2(k01[1], u1, acc);
                    acc = fma2(k01[2], u2, acc);
                    acc = fma2(k01[3], u3, acc);
                    float lo, hi;
                    unpack2(acc, lo, hi);
                    v[q + i2] = lo + hi;
                }
            }

            // butterfly over the 8 group lanes, 16 timesteps at once.
            // ends: v[0] = y-partial(t=tb+gl), v[8] = y-partial(t=tb+8+gl)
            {
                const bool h4 = (gl & 4) != 0;
#pragma unroll
                for (int ii = 0; ii < 8; ++ii) {
                    const int i = (ii < 4) ? ii : ii + 4;      // {0..3, 8..11}
                    const float send = h4 ? v[i] : v[i + 4];
                    const float keep = h4 ? v[i + 4] : v[i];
                    v[i] = keep + __shfl_xor_sync(0xFFFFFFFFu, send, 4);
                }
                const bool h2 = (gl & 2) != 0;
#pragma unroll
                for (int ii = 0; ii < 4; ++ii) {
                    const int i = (ii < 2) ? ii : ii + 6;      // {0,1, 8,9}
                    const float send = h2 ? v[i] : v[i + 2];
                    const float keep = h2 ? v[i + 2] : v[i];
                    v[i] = keep + __shfl_xor_sync(0xFFFFFFFFu, send, 2);
                }
                const bool h1 = (gl & 1) != 0;
#pragma unroll
                for (int ii = 0; ii < 2; ++ii) {
                    const int i = ii * 8;                      // {0, 8}
                    const float send = h1 ? v[i] : v[i + 1];
                    const float keep = h1 ? v[i + 1] : v[i];
                    v[i] = keep + __shfl_xor_sync(0xFFFFFFFFu, send, 1);
                }
            }

            // transpose to store layout: dst lane (si,sj) takes from lane sj*8+si
            const int srcLane = sj * 8 + si;
            y_out[tb / 8]     = __shfl_sync(0xFFFFFFFFu, v[0], srcLane);
            y_out[tb / 8 + 1] = __shfl_sync(0xFFFFFFFFu, v[8], srcLane);
        }

        // store tile r with fused skip connection
#pragma unroll
        for (int k = 0; k < 4; ++k)
            yg[(l0 + si + 8 * k) * D_MODEL] = fmaf(Dd, xcur[k], y_out[k]);
    }
}

} // namespace

extern "C" void kernel_launch(void* const* d_in, const int* in_sizes, int n_in,
                              void* d_out, int out_size)
{
    const float* x     = (const float*)d_in[0];
    const float* log_A = (const float*)d_in[1];
    const float* Bp    = (const float*)d_in[2];
    const float* Cp    = (const float*)d_in[3];
    const float* Dp    = (const float*)d_in[4];
    float* y           = (float*)d_out;

    dim3 grid(D_MODEL / 8, BATCH);
    ssm_scan_kernel<<<grid, THREADS>>>(x, log_A, Bp, Cp, Dp, y);
}

// round 6
// speedup vs baseline: 1.8228x; 1.8228x over previous
#include <cuda_runtime.h>

// VanillaSSM via exact diagonal recurrence (== reference FFT conv):
//   u[d,n](l) = A_bar[d,n]*u(l-1) + x[b,l,d]
//   y[b,l,d]  = sum_n (C*B_bar)[d,n]*u[d,n](l) + D[d]*x[b,l,d]
//
// Key structure: when A_bar[d,:] is uniform in n (true for this problem:
// log_A == 0 => A_bar = exp(-0.1) everywhere), all 64 states of a d are
// identical, so y = K_d*u + D_d*x with ONE scalar recurrence per (b,d).
// A setup kernel verifies this on-device per d and reduces K_d; a fast
// memory-bound kernel runs iff all-uniform, else the general (R5) kernel
// runs. Both are always launched; exactly one does work. Deterministic,
// graph-capturable, no allocations (scratch in __device__ globals).

namespace {

constexpr int BATCH   = 8;
constexpr int L       = 2048;
constexpr int D_MODEL = 1024;
constexpr int NSTATE  = 64;
constexpr float DT    = 0.1f;

// ---------------- scratch (persistent; rewritten every launch) -----------
__device__ float g_K[D_MODEL];
__device__ float g_a[D_MODEL];
__device__ int   g_uni[8];

// ---------------- packed f32x2 helpers (general path) --------------------
__device__ __forceinline__ unsigned long long pack2(float lo, float hi) {
    unsigned long long r;
    asm("mov.b64 %0, {%1, %2};" : "=l"(r) : "f"(lo), "f"(hi));
    return r;
}
__device__ __forceinline__ void unpack2(unsigned long long v, float& lo, float& hi) {
    asm("mov.b64 {%0, %1}, %2;" : "=f"(lo), "=f"(hi) : "l"(v));
}
__device__ __forceinline__ unsigned long long mul2(unsigned long long a, unsigned long long b) {
    unsigned long long r;
    asm("mul.rn.f32x2 %0, %1, %2;" : "=l"(r) : "l"(a), "l"(b));
    return r;
}
__device__ __forceinline__ unsigned long long fma2(unsigned long long a, unsigned long long b,
                                                   unsigned long long c) {
    unsigned long long r;
    asm("fma.rn.f32x2 %0, %1, %2, %3;" : "=l"(r) : "l"(a), "l"(b), "l"(c));
    return r;
}
__device__ __forceinline__ void prefetchL2(const float* p) {
    asm volatile("prefetch.global.L2 [%0];" :: "l"(p));
}

// ================= setup: coefficients + uniformity check ================
// grid 8 x 128 threads; thread owns one d, loops its 64 states serially.
__global__ void ssm_setup_kernel(const float* __restrict__ log_A,
                                 const float* __restrict__ Bp,
                                 const float* __restrict__ Cp)
{
    __shared__ int s_uni;
    if (threadIdx.x == 0) s_uni = 1;
    __syncthreads();

    const int d = blockIdx.x * 128 + threadIdx.x;
    float K = 0.0f, a0 = 0.0f;
    bool uni = true;
#pragma unroll 4
    for (int n = 0; n < NSTATE; ++n) {
        const int i = d * NSTATE + n;
        const float A = -expf(log_A[i]);
        const float a = expf(DT * A);
        K += (a - 1.0f) / A * Bp[i] * Cp[i];
        if (n == 0) a0 = a;
        else uni = uni && (__float_as_int(a) == __float_as_int(a0));
    }
    g_K[d] = K;
    g_a[d] = a0;
    if (!uni) s_uni = 0;          // benign race: all writers store 0
    __syncthreads();
    if (threadIdx.x == 0) g_uni[blockIdx.x] = s_uni;
}

__device__ __forceinline__ bool all_uniform() {
    int u = 1;
#pragma unroll
    for (int i = 0; i < 8; ++i) u &= g_uni[i];
    return u != 0;
}

// ================= fast path: one scalar recurrence per (b,d) ============
// grid 256 x 32: block = one warp = 32 consecutive d of one b chunk.
constexpr int G  = 16;            // elements per stage
constexpr int NG = L / G;         // 128 stages

__global__ __launch_bounds__(32)
void ssm_fast_kernel(const float* __restrict__ x,
                     const float* __restrict__ Dp,
                     float* __restrict__ y)
{
    if (!all_uniform()) return;

    const int beta = blockIdx.x;
    const int b    = beta >> 5;
    const int d    = (beta & 31) * 32 + threadIdx.x;

    const float a  = g_a[d];
    const float K  = g_K[d];
    const float Dd = Dp[d];

    const float* xg = x + (long)b * L * D_MODEL + d;
    float*       yg = y + (long)b * L * D_MODEL + d;

    float b0[G], b1[G];
    // stage 0 load + L2 prefetch of stage 1
#pragma unroll
    for (int i = 0; i < G; ++i) b0[i] = xg[i * D_MODEL];
#pragma unroll
    for (int i = 0; i < G; ++i) prefetchL2(xg + (G + i) * D_MODEL);

    float u = 0.0f;
#pragma unroll 4
    for (int rr = 0; rr < NG; rr += 2) {
        // phase A: prefetch rr+2, load rr+1 -> b1, compute rr from b0
        if (rr + 2 < NG) {
            const float* p = xg + (rr + 2) * G * D_MODEL;
#pragma unroll
            for (int i = 0; i < G; ++i) prefetchL2(p + i * D_MODEL);
        }
        {
            const float* p = xg + (rr + 1) * G * D_MODEL;
#pragma unroll
            for (int i = 0; i < G; ++i) b1[i] = p[i * D_MODEL];
        }
        {
            float* q = yg + rr * G * D_MODEL;
#pragma unroll
            for (int i = 0; i < G; ++i) {
                const float xv = b0[i];
                u = fmaf(a, u, xv);
                q[i * D_MODEL] = fmaf(Dd, xv, K * u);
            }
        }
        // phase B: prefetch rr+3, load rr+2 -> b0, compute rr+1 from b1
        if (rr + 3 < NG) {
            const float* p = xg + (rr + 3) * G * D_MODEL;
#pragma unroll
            for (int i = 0; i < G; ++i) prefetchL2(p + i * D_MODEL);
        }
        if (rr + 2 < NG) {
            const float* p = xg + (rr + 2) * G * D_MODEL;
#pragma unroll
            for (int i = 0; i < G; ++i) b0[i] = p[i * D_MODEL];
        }
        {
            float* q = yg + (rr + 1) * G * D_MODEL;
#pragma unroll
            for (int i = 0; i < G; ++i) {
                const float xv = b1[i];
                u = fmaf(a, u, xv);
                q[i * D_MODEL] = fmaf(Dd, xv, K * u);
            }
        }
    }
}

// ================= general fallback (proven R5 kernel) ===================
constexpr int T       = 32;
constexpr int NROUNDS = L / T;
constexpr int THREADS = 64;
constexpr int XSTR    = 40;

__global__ __launch_bounds__(THREADS)
void ssm_scan_kernel(const float* __restrict__ x,
                     const float* __restrict__ log_A,
                     const float* __restrict__ Bp,
                     const float* __restrict__ Cp,
                     const float* __restrict__ Dp,
                     float* __restrict__ y)
{
    if (all_uniform()) return;    // fast path handled everything

    __shared__ float xs[2][2][4 * XSTR];

    const int b    = blockIdx.y;
    const int tid  = threadIdx.x;
    const int w    = tid >> 5;
    const int lane = tid & 31;
    const int g    = lane >> 3;
    const int gl   = lane & 7;
    const int d0w  = blockIdx.x * 8 + w * 4;
    const int d    = d0w + g;

    unsigned long long a01[4], k01[4];
    {
        const int cb = d * NSTATE + gl * 4;
        const float4 laL = *(const float4*)&log_A[cb];
        const float4 laH = *(const float4*)&log_A[cb + 32];
        const float4 bL  = *(const float4*)&Bp[cb];
        const float4 bH  = *(const float4*)&Bp[cb + 32];
        const float4 cL  = *(const float4*)&Cp[cb];
        const float4 cH  = *(const float4*)&Cp[cb + 32];
        const float* laLp = &laL.x; const float* laHp = &laH.x;
        const float* bLp  = &bL.x;  const float* bHp  = &bH.x;
        const float* cLp  = &cL.x;  const float* cHp  = &cH.x;
#pragma unroll
        for (int j = 0; j < 4; ++j) {
            const float AL = -expf(laLp[j]);
            const float AH = -expf(laHp[j]);
            const float aL = expf(DT * AL);
            const float aH = expf(DT * AH);
            a01[j] = pack2(aL, aH);
            k01[j] = pack2((aL - 1.0f) / AL * bLp[j] * cLp[j],
                           (aH - 1.0f) / AH * bHp[j] * cHp[j]);
        }
    }

    const int si = lane >> 2;
    const int sj = lane & 3;
    const float Dd = Dp[d0w + sj];
    const float* xg = x + (long)b * L * D_MODEL + d0w + sj;
    float*       yg = y + (long)b * L * D_MODEL + d0w + sj;

    float xpre[4], xcur[4];
#pragma unroll
    for (int k = 0; k < 4; ++k)
        xpre[k] = xg[(si + 8 * k) * D_MODEL];

    unsigned long long u0 = 0ull, u1 = 0ull, u2 = 0ull, u3 = 0ull;

    for (int r = 0; r < NROUNDS; ++r) {
        const int l0 = r * T;
        float* xb = xs[w][r & 1];
#pragma unroll
        for (int k = 0; k < 4; ++k) {
            xcur[k] = xpre[k];
            xb[sj * XSTR + si + 8 * k] = xpre[k];
        }
        __syncwarp();
        if (r + 1 < NROUNDS) {
#pragma unroll
            for (int k = 0; k < 4; ++k)
                xpre[k] = xg[(l0 + T + si + 8 * k) * D_MODEL];
        }

        float y_out[4];
#pragma unroll
        for (int tb = 0; tb < T; tb += 16) {
            float v[16];
#pragma unroll
            for (int q = 0; q < 16; q += 4) {
                const float4 xq = *(const float4*)&xb[g * XSTR + tb + q];
                const float* xe = &xq.x;
#pragma unroll
                for (int i2 = 0; i2 < 4; ++i2) {
                    const unsigned long long xx = pack2(xe[i2], xe[i2]);
                    u0 = fma2(a01[0], u0, xx);
                    u1 = fma2(a01[1], u1, xx);
                    u2 = fma2(a01[2], u2, xx);
                    u3 = fma2(a01[3], u3, xx);
                    unsigned long long acc = mul2(k01[0], u0);
                    acc = fma2(k01[1], u1, acc);
                    acc = fma2(k01[2], u2, acc);
                    float lo, hi;
                    unpack2(fma2(k01[3], u3, acc), lo, hi);
                    v[q + i2] = lo + hi;
                }
            }
            {
                const bool h4 = (gl & 4) != 0;
#pragma unroll
                for (int ii = 0; ii < 8; ++ii) {
                    const int i = (ii < 4) ? ii : ii + 4;
                    const float send = h4 ? v[i] : v[i + 4];
                    const float keep = h4 ? v[i + 4] : v[i];
                    v[i] = keep + __shfl_xor_sync(0xFFFFFFFFu, send, 4);
                }
                const bool h2 = (gl & 2) != 0;
#pragma unroll
                for (int ii = 0; ii < 4; ++ii) {
                    const int i = (ii < 2) ? ii : ii + 6;
                    const float send = h2 ? v[i] : v[i + 2];
                    const float keep = h2 ? v[i + 2] : v[i];
                    v[i] = keep + __shfl_xor_sync(0xFFFFFFFFu, send, 2);
                }
                const bool h1 = (gl & 1) != 0;
#pragma unroll
                for (int ii = 0; ii < 2; ++ii) {
                    const int i = ii * 8;
                    const float send = h1 ? v[i] : v[i + 1];
                    const float keep = h1 ? v[i + 1] : v[i];
                    v[i] = keep + __shfl_xor_sync(0xFFFFFFFFu, send, 1);
                }
            }
            const int srcLane = sj * 8 + si;
            y_out[tb / 8]     = __shfl_sync(0xFFFFFFFFu, v[0], srcLane);
            y_out[tb / 8 + 1] = __shfl_sync(0xFFFFFFFFu, v[8], srcLane);
        }
#pragma unroll
        for (int k = 0; k < 4; ++k)
            yg[(l0 + si + 8 * k) * D_MODEL] = fmaf(Dd, xcur[k], y_out[k]);
    }
}

} // namespace

extern "C" void kernel_launch(void* const* d_in, const int* in_sizes, int n_in,
                              void* d_out, int out_size)
{
    const float* x     = (const float*)d_in[0];
    const float* log_A = (const float*)d_in[1];
    const float* Bp    = (const float*)d_in[2];
    const float* Cp    = (const float*)d_in[3];
    const float* Dp    = (const float*)d_in[4];
    float* y           = (float*)d_out;

    ssm_setup_kernel<<<8, 128>>>(log_A, Bp, Cp);
    ssm_fast_kernel<<<BATCH * 32, 32>>>(x, Dp, y);
    dim3 grid(D_MODEL / 8, BATCH);
    ssm_scan_kernel<<<grid, THREADS>>>(x, log_A, Bp, Cp, Dp, y);
}

// round 9
// speedup vs baseline: 2.3185x; 1.2719x over previous
#include <cuda_runtime.h>

// VanillaSSM via exact diagonal recurrence (== reference FFT conv).
// Structure exploited: when A_bar[d,:] is uniform in n (true here: log_A==0),
// all 64 states of a d are identical => y = K_d*u + D_d*x with ONE scalar
// recurrence u(l) = a*u(l-1) + x(l) per (b,d). Verified on-device; general
// scan kernel is the fallback (exactly one path does work per launch).
//
// Fast path is a chunked scan for parallelism (exact, no truncation):
//   A: per (b,d,chunk) end-state S_c = sum_i a^(CH-1-i) x_i   (reads x;
//      last chunk skipped -- its carry is never consumed)
//   B: u0(c) = Horner(a^CH, S_0..S_{c-1}); replay chunk, write y.
// C=8 chunks of 256 -> 65536 independent streams (~14 warps/SM in flight).

namespace {

constexpr int BATCH   = 8;
constexpr int L       = 2048;
constexpr int D_MODEL = 1024;
constexpr int NSTATE  = 64;
constexpr float DT    = 0.1f;

constexpr int C  = 8;            // chunks per sequence
constexpr int CH = L / C;        // 256 steps per chunk

// ---------------- scratch (persistent; rewritten every launch) -----------
__device__ float g_K[D_MODEL];
__device__ float g_a[D_MODEL];
__device__ int   g_uni[8];
__device__ float g_S[BATCH * C * D_MODEL];   // chunk end-states

// ---------------- packed f32x2 helpers (general fallback) ----------------
__device__ __forceinline__ unsigned long long pack2(float lo, float hi) {
    unsigned long long r;
    asm("mov.b64 %0, {%1, %2};" : "=l"(r) : "f"(lo), "f"(hi));
    return r;
}
__device__ __forceinline__ void unpack2(unsigned long long v, float& lo, float& hi) {
    asm("mov.b64 {%0, %1}, %2;" : "=f"(lo), "=f"(hi) : "l"(v));
}
__device__ __forceinline__ unsigned long long mul2(unsigned long long a, unsigned long long b) {
    unsigned long long r;
    asm("mul.rn.f32x2 %0, %1, %2;" : "=l"(r) : "l"(a), "l"(b));
    return r;
}
__device__ __forceinline__ unsigned long long fma2(unsigned long long a, unsigned long long b,
                                                   unsigned long long c) {
    unsigned long long r;
    asm("fma.rn.f32x2 %0, %1, %2, %3;" : "=l"(r) : "l"(a), "l"(b), "l"(c));
    return r;
}

__device__ __forceinline__ bool all_uniform() {
    int u = 1;
#pragma unroll
    for (int i = 0; i < 8; ++i) u &= g_uni[i];
    return u != 0;
}

// ================= setup: coefficients + uniformity check ================
// 8 blocks x 1024 threads: 8 threads per d, 8 states per thread.
__global__ __launch_bounds__(1024)
void ssm_setup_kernel(const float* __restrict__ log_A,
                      const float* __restrict__ Bp,
                      const float* __restrict__ Cp)
{
    __shared__ int s_uni;
    if (threadIdx.x == 0) s_uni = 1;
    __syncthreads();

    const int tid  = threadIdx.x;
    const int d    = blockIdx.x * 128 + (tid >> 3);
    const int n0   = (tid & 7) * 8;
    const int base = d * NSTATE + n0;

    const float4 la0 = *(const float4*)&log_A[base];
    const float4 la1 = *(const float4*)&log_A[base + 4];
    const float4 bp0 = *(const float4*)&Bp[base];
    const float4 bp1 = *(const float4*)&Bp[base + 4];
    const float4 cp0 = *(const float4*)&Cp[base];
    const float4 cp1 = *(const float4*)&Cp[base + 4];

    float la[8] = {la0.x, la0.y, la0.z, la0.w, la1.x, la1.y, la1.z, la1.w};
    float bp[8] = {bp0.x, bp0.y, bp0.z, bp0.w, bp1.x, bp1.y, bp1.z, bp1.w};
    float cp[8] = {cp0.x, cp0.y, cp0.z, cp0.w, cp1.x, cp1.y, cp1.z, cp1.w};

    float K = 0.0f, a[8];
    bool uni = true;
#pragma unroll
    for (int j = 0; j < 8; ++j) {
        const float A = -expf(la[j]);
        a[j] = expf(DT * A);
        K += (a[j] - 1.0f) / A * bp[j] * cp[j];
        uni = uni && (__float_as_int(a[j]) == __float_as_int(a[0]));
    }
    // compare against the d-group leader's a (lanes tid&~7 .. +7 share a d)
    const float aref = __shfl_sync(0xFFFFFFFFu, a[0], (tid & 31) & ~7);
    uni = uni && (__float_as_int(a[0]) == __float_as_int(aref));

    // sum K over the 8-lane group
#pragma unroll
    for (int off = 1; off < 8; off <<= 1)
        K += __shfl_xor_sync(0xFFFFFFFFu, K, off);

    if ((tid & 7) == 0) { g_K[d] = K; g_a[d] = aref; }
    if (__ballot_sync(0xFFFFFFFFu, !uni) != 0) s_uni = 0;   // benign race
    __syncthreads();
    if (threadIdx.x == 0) g_uni[blockIdx.x] = s_uni;
}

// ================= fast path A: chunk end-states =========================
// grid (D_MODEL/256, C-1, BATCH), block 256: thread -> (b, chunk, d).
__global__ __launch_bounds__(256)
void ssm_carry_kernel(const float* __restrict__ x)
{
    if (!all_uniform()) return;

    const int d = blockIdx.x * 256 + threadIdx.x;
    const int c = blockIdx.y;
    const int b = blockIdx.z;
    const float a = g_a[d];

    const float* xg = x + ((long)b * L + c * CH) * D_MODEL + d;

    float u = 0.0f;
#pragma unroll 8
    for (int i = 0; i < CH; ++i)
        u = fmaf(a, u, xg[i * D_MODEL]);

    g_S[(b * C + c) * D_MODEL + d] = u;
}

// ================= fast path B: seeded replay, writes y ==================
__global__ __launch_bounds__(256)
void ssm_fast_kernel(const float* __restrict__ x,
                     const float* __restrict__ Dp,
                     float* __restrict__ y)
{
    if (!all_uniform()) return;

    const int d = blockIdx.x * 256 + threadIdx.x;
    const int c = blockIdx.y;
    const int b = blockIdx.z;

    const float a  = g_a[d];
    const float K  = g_K[d];
    const float Dd = Dp[d];

    // a^CH via squarings (CH = 256 = 2^8)
    float ap = a;
#pragma unroll
    for (int k = 0; k < 8; ++k) ap *= ap;

    // exact seed: u0 = sum_{j<c} ap^(c-1-j) * S_j   (Horner)
    float u = 0.0f;
    for (int j = 0; j < c; ++j)
        u = fmaf(ap, u, g_S[(b * C + j) * D_MODEL + d]);

    const float* xg = x + ((long)b * L + c * CH) * D_MODEL + d;
    float*       yg = y + ((long)b * L + c * CH) * D_MODEL + d;

#pragma unroll 8
    for (int i = 0; i < CH; ++i) {
        const float xv = xg[i * D_MODEL];
        u = fmaf(a, u, xv);
        yg[i * D_MODEL] = fmaf(Dd, xv, K * u);
    }
}

// ================= general fallback (proven R5 kernel) ===================
constexpr int T       = 32;
constexpr int NROUNDS = L / T;
constexpr int THREADS = 64;
constexpr int XSTR    = 40;

__global__ __launch_bounds__(THREADS)
void ssm_scan_kernel(const float* __restrict__ x,
                     const float* __restrict__ log_A,
                     const float* __restrict__ Bp,
                     const float* __restrict__ Cp,
                     const float* __restrict__ Dp,
                     float* __restrict__ y)
{
    if (all_uniform()) return;    // fast path handled everything

    __shared__ float xs[2][2][4 * XSTR];

    const int b    = blockIdx.y;
    const int tid  = threadIdx.x;
    const int w    = tid >> 5;
    const int lane = tid & 31;
    const int g    = lane >> 3;
    const int gl   = lane & 7;
    const int d0w  = blockIdx.x * 8 + w * 4;
    const int d    = d0w + g;

    unsigned long long a01[4], k01[4];
    {
        const int cb = d * NSTATE + gl * 4;
        const float4 laL = *(const float4*)&log_A[cb];
        const float4 laH = *(const float4*)&log_A[cb + 32];
        const float4 bL  = *(const float4*)&Bp[cb];
        const float4 bH  = *(const float4*)&Bp[cb + 32];
        const float4 cL  = *(const float4*)&Cp[cb];
        const float4 cH  = *(const float4*)&Cp[cb + 32];
        const float* laLp = &laL.x; const float* laHp = &laH.x;
        const float* bLp  = &bL.x;  const float* bHp  = &bH.x;
        const float* cLp  = &cL.x;  const float* cHp  = &cH.x;
#pragma unroll
        for (int j = 0; j < 4; ++j) {
            const float AL = -expf(laLp[j]);
            const float AH = -expf(laHp[j]);
            const float aL = expf(DT * AL);
            const float aH = expf(DT * AH);
            a01[j] = pack2(aL, aH);
            k01[j] = pack2((aL - 1.0f) / AL * bLp[j] * cLp[j],
                           (aH - 1.0f) / AH * bHp[j] * cHp[j]);
        }
    }

    const int si = lane >> 2;
    const int sj = lane & 3;
    const float Dd = Dp[d0w + sj];
    const float* xg = x + (long)b * L * D_MODEL + d0w + sj;
    float*       yg = y + (long)b * L * D_MODEL + d0w + sj;

    float xpre[4], xcur[4];
#pragma unroll
    for (int k = 0; k < 4; ++k)
        xpre[k] = xg[(si + 8 * k) * D_MODEL];

    unsigned long long u0 = 0ull, u1 = 0ull, u2 = 0ull, u3 = 0ull;

    for (int r = 0; r < NROUNDS; ++r) {
        const int l0 = r * T;
        float* xb = xs[w][r & 1];
#pragma unroll
        for (int k = 0; k < 4; ++k) {
            xcur[k] = xpre[k];
            xb[sj * XSTR + si + 8 * k] = xpre[k];
        }
        __syncwarp();
        if (r + 1 < NROUNDS) {
#pragma unroll
            for (int k = 0; k < 4; ++k)
                xpre[k] = xg[(l0 + T + si + 8 * k) * D_MODEL];
        }

        float y_out[4];
#pragma unroll
        for (int tb = 0; tb < T; tb += 16) {
            float v[16];
#pragma unroll
            for (int q = 0; q < 16; q += 4) {
                const float4 xq = *(const float4*)&xb[g * XSTR + tb + q];
                const float* xe = &xq.x;
#pragma unroll
                for (int i2 = 0; i2 < 4; ++i2) {
                    const unsigned long long xx = pack2(xe[i2], xe[i2]);
                    u0 = fma2(a01[0], u0, xx);
                    u1 = fma2(a01[1], u1, xx);
                    u2 = fma2(a01[2], u2, xx);
                    u3 = fma2(a01[3], u3, xx);
                    unsigned long long acc = mul2(k01[0], u0);
                    acc = fma2(k01[1], u1, acc);
                    acc = fma2(k01[2], u2, acc);
                    float lo, hi;
                    unpack2(fma2(k01[3], u3, acc), lo, hi);
                    v[q + i2] = lo + hi;
                }
            }
            {
                const bool h4 = (gl & 4) != 0;
#pragma unroll
                for (int ii = 0; ii < 8; ++ii) {
                    const int i = (ii < 4) ? ii : ii + 4;
                    const float send = h4 ? v[i] : v[i + 4];
                    const float keep = h4 ? v[i + 4] : v[i];
                    v[i] = keep + __shfl_xor_sync(0xFFFFFFFFu, send, 4);
                }
                const bool h2 = (gl & 2) != 0;
#pragma unroll
                for (int ii = 0; ii < 4; ++ii) {
                    const int i = (ii < 2) ? ii : ii + 6;
                    const float send = h2 ? v[i] : v[i + 2];
                    const float keep = h2 ? v[i + 2] : v[i];
                    v[i] = keep + __shfl_xor_sync(0xFFFFFFFFu, send, 2);
                }
                const bool h1 = (gl & 1) != 0;
#pragma unroll
                for (int ii = 0; ii < 2; ++ii) {
                    const int i = ii * 8;
                    const float send = h1 ? v[i] : v[i + 1];
                    const float keep = h1 ? v[i + 1] : v[i];
                    v[i] = keep + __shfl_xor_sync(0xFFFFFFFFu, send, 1);
                }
            }
            const int srcLane = sj * 8 + si;
            y_out[tb / 8]     = __shfl_sync(0xFFFFFFFFu, v[0], srcLane);
            y_out[tb / 8 + 1] = __shfl_sync(0xFFFFFFFFu, v[8], srcLane);
        }
#pragma unroll
        for (int k = 0; k < 4; ++k)
            yg[(l0 + si + 8 * k) * D_MODEL] = fmaf(Dd, xcur[k], y_out[k]);
    }
}

} // namespace

extern "C" void kernel_launch(void* const* d_in, const int* in_sizes, int n_in,
                              void* d_out, int out_size)
{
    const float* x     = (const float*)d_in[0];
    const float* log_A = (const float*)d_in[1];
    const float* Bp    = (const float*)d_in[2];
    const float* Cp    = (const float*)d_in[3];
    const float* Dp    = (const float*)d_in[4];
    float* y           = (float*)d_out;

    ssm_setup_kernel<<<8, 1024>>>(log_A, Bp, Cp);

    dim3 agrid(D_MODEL / 256, C - 1, BATCH);    // last chunk's carry unused
    ssm_carry_kernel<<<agrid, 256>>>(x);
    dim3 bgrid(D_MODEL / 256, C, BATCH);
    ssm_fast_kernel<<<bgrid, 256>>>(x, Dp, y);

    dim3 sgrid(D_MODEL / 8, BATCH);
    ssm_scan_kernel<<<sgrid, THREADS>>>(x, log_A, Bp, Cp, Dp, y);
}